// round 11
// baseline (speedup 1.0000x reference)
#include <cuda_runtime.h>
#include <cuda_fp16.h>

#define NN      256     // neurons (post)
#define NI      128     // sensory inputs
#define BATCH   1024
#define UNFOLDS 6
#define NB      4       // batch rows per CTA = 2 half2 pairs (256*4 = 1024 exact)
#define NPAIR   2
#define GRID    256
#define NT      512     // 2 groups of 256; group g reduces half the pre range
#define CHUNK   4       // j's per fp16 accumulator before fp32 flush

// Recurrent weights in fp16 (duplicated half2 lanes), with c split into
// hi+lo fp16 parts for accuracy:  z = a*v + c_hi + c_lo,
// a = sigma/2, c = -sigma*mu/2, p = W*erev/2, q = W/2.
// sigmoid(sigma*(v-mu)) = 0.5 + 0.5*tanh(z); constant halves folded into
// g_knum/g_kden (fp32, from raw inputs).
// Sensory weights stay fully fp32 (one-time pass; avoids persistent bias).
struct alignas(16) WH { __half2 a, chi, p, q; };

__device__ WH      gh_rec[NN * NN];   // recurrent, [pre j][post n]
__device__ __half2 gh_clo[NN * NN];   // c_lo residuals
__device__ float4  g_senf[NI * NN];   // sensory fp32: (a, c, p, q)
__device__ float   g_knum[NN];        // gleak*vleak + sum over pre of P (fp32)
__device__ float   g_kden[NN];        // cm + gleak + sum over pre of Q (fp32)

__device__ __forceinline__ float tanh_fast(float x) {
    float y;
    asm("tanh.approx.f32 %0, %1;" : "=f"(y) : "f"(x));
    return y;
}
__device__ __forceinline__ __half2 tanh2_fast(__half2 x) {
    __half2 y;
    asm("tanh.approx.f16x2 %0, %1;"
        : "=r"(*reinterpret_cast<unsigned*>(&y))
        : "r"(*reinterpret_cast<unsigned*>(&x)));
    return y;
}
__device__ __forceinline__ __half2 u2h(unsigned v) {
    __half2 h;
    *reinterpret_cast<unsigned*>(&h) = v;
    return h;
}

// ---------------------------------------------------------------------------
// Prep kernels
// ---------------------------------------------------------------------------
__global__ void pack_rec_kernel(const float* __restrict__ mu,
                                const float* __restrict__ sigma,
                                const float* __restrict__ W,
                                const float* __restrict__ erev) {
    int idx = blockIdx.x * NN + threadIdx.x;   // j * NN + n
    float a = 0.5f * sigma[idx];
    float m = mu[idx];
    float q = 0.5f * W[idx];
    float e = erev[idx];
    float c = -a * m;
    __half chi = __float2half_rn(c);
    float clo = c - __half2float(chi);
    WH w;
    w.a   = __float2half2_rn(a);
    w.chi = __half2half2(chi);
    w.p   = __float2half2_rn(q * e);
    w.q   = __float2half2_rn(q);
    gh_rec[idx] = w;
    gh_clo[idx] = __float2half2_rn(clo);
}

__global__ void pack_sen_kernel(const float* __restrict__ smu,
                                const float* __restrict__ ssigma,
                                const float* __restrict__ sW,
                                const float* __restrict__ serev) {
    int idx = blockIdx.x * NN + threadIdx.x;   // i * NN + n
    float a = 0.5f * ssigma[idx];
    float m = smu[idx];
    float q = 0.5f * sW[idx];
    float e = serev[idx];
    g_senf[idx] = make_float4(a, -a * m, q * e, q);
}

__global__ void reduce_k_kernel(const float* __restrict__ W,
                                const float* __restrict__ erev,
                                const float* __restrict__ sW,
                                const float* __restrict__ serev,
                                const float* __restrict__ vleak,
                                const float* __restrict__ gleak,
                                const float* __restrict__ cm_t) {
    __shared__ float rp[128];
    __shared__ float rq[128];
    int n = blockIdx.x;
    int t = threadIdx.x;
    float sp = 0.0f, sq = 0.0f;
    for (int j = t; j < NN; j += 128) {
        float q = 0.5f * W[j * NN + n];
        sp += q * erev[j * NN + n];
        sq += q;
    }
    for (int i = t; i < NI; i += 128) {
        float q = 0.5f * sW[i * NN + n];
        sp += q * serev[i * NN + n];
        sq += q;
    }
    rp[t] = sp; rq[t] = sq;
    __syncthreads();
    for (int s = 64; s > 0; s >>= 1) {
        if (t < s) { rp[t] += rp[t + s]; rq[t] += rq[t + s]; }
        __syncthreads();
    }
    if (t == 0) {
        g_knum[n] = fmaf(gleak[n], vleak[n], rp[0]);
        g_kden[n] = cm_t[n] + gleak[n] + rq[0];
    }
}

// ---------------------------------------------------------------------------
// Main: 2 CTAs/SM, 512 threads = 2 groups x 256. Thread owns output neuron
// n = tid&255; group g = tid>>8 reduces half the presynaptic range.
// Sensory pass fp32; recurrent inner loop fp16x2 on row pairs with c-split
// args and fp16 accumulators flushed to fp32 every CHUNK j's.
// State/division/output fp32.
// ---------------------------------------------------------------------------
__global__ __launch_bounds__(NT, 2) void liquid_main_kernel(
    const float* __restrict__ inputs,
    const float* __restrict__ state,
    const float* __restrict__ map_w,
    const float* __restrict__ map_b,
    const float* __restrict__ cm_t,
    float* __restrict__ out,
    int copies) {

    __shared__ float   sxf[NB][NI];      // mapped inputs (fp32, for sensory)
    __shared__ __half2 sv2[NN][NPAIR];   // v state as fp16 pairs: [j][pair]
    __shared__ float   pnum[NB][NN];     // group-1 partial numerators (fp32)
    __shared__ float   pden[NB][NN];     // group-1 partial denominators

    const int tid = threadIdx.x;
    const int n   = tid & (NN - 1);
    const int g   = tid >> 8;            // 0 or 1
    const int r0  = blockIdx.x * NB;

    // Load + map inputs (fp32)
    for (int idx = tid; idx < NB * NI; idx += NT) {
        int bb = idx >> 7;
        int i  = idx & (NI - 1);
        sxf[bb][i] = fmaf(inputs[(r0 + bb) * NI + i], map_w[i], map_b[i]);
    }
    // Load v state into half2 pairs: sv2[j][p] = (v[2p][j], v[2p+1][j])
    {
        int j = tid >> 1;
        int p = tid & 1;
        sv2[j][p] = __floats2half2_rn(state[(r0 + 2 * p)     * NN + j],
                                      state[(r0 + 2 * p + 1) * NN + j]);
    }
    // fp32 state registers (group 0 uses them for cm*v and division)
    float vf[NB];
    #pragma unroll
    for (int bb = 0; bb < NB; bb++) vf[bb] = state[(r0 + bb) * NN + n];
    __syncthreads();

    const float cmn = cm_t[n];

    // ---- Sensory pass (fp32): group g reduces i in [g*64, g*64+64) ----
    float snum[NB], sden[NB];
    #pragma unroll
    for (int bb = 0; bb < NB; bb++) { snum[bb] = 0.0f; sden[bb] = 0.0f; }
    {
        const int ib = g * (NI / 2);
        #pragma unroll 4
        for (int ii = 0; ii < NI / 2; ii++) {
            float4 w = g_senf[(ib + ii) * NN + n];
            #pragma unroll
            for (int bb = 0; bb < NB; bb++) {
                float z = fmaf(w.x, sxf[bb][ib + ii], w.y);
                float t = tanh_fast(z);
                snum[bb] = fmaf(w.z, t, snum[bb]);
                sden[bb] = fmaf(w.w, t, sden[bb]);
            }
        }
    }
    if (g == 1) {
        #pragma unroll
        for (int bb = 0; bb < NB; bb++) { pnum[bb][n] = snum[bb]; pden[bb][n] = sden[bb]; }
    }
    __syncthreads();
    if (g == 0) {
        const float kn = g_knum[n];
        const float kd = g_kden[n];
        #pragma unroll
        for (int bb = 0; bb < NB; bb++) {
            snum[bb] += pnum[bb][n] + kn;
            sden[bb] += pden[bb][n] + kd;
        }
    }
    __syncthreads();   // pnum/pden free for reuse

    const int jb = g * (NN / 2);

    // ---- Unfold loop (fp16x2 recurrent reduction) ----
    for (int step = 0; step < UNFOLDS; step++) {
        float num[NB], den[NB];
        if (g == 0) {
            #pragma unroll
            for (int bb = 0; bb < NB; bb++) {
                num[bb] = fmaf(cmn, vf[bb], snum[bb]);
                den[bb] = sden[bb];
            }
        } else {
            #pragma unroll
            for (int bb = 0; bb < NB; bb++) { num[bb] = 0.0f; den[bb] = 0.0f; }
        }

        for (int ch = 0; ch < (NN / 2) / CHUNK; ch++) {
            __half2 hn0 = __float2half2_rn(0.0f), hd0 = hn0;
            __half2 hn1 = hn0, hd1 = hn0;
            #pragma unroll
            for (int cj = 0; cj < CHUNK; cj++) {
                int j = jb + ch * CHUNK + cj;
                uint4 u = *reinterpret_cast<const uint4*>(gh_rec + j * NN + n);
                __half2 wa = u2h(u.x), wchi = u2h(u.y), wp = u2h(u.z), wq = u2h(u.w);
                __half2 clo = gh_clo[j * NN + n];
                __half2 v01 = sv2[j][0];
                __half2 v23 = sv2[j][1];
                __half2 t0 = tanh2_fast(__hadd2(__hfma2(wa, v01, wchi), clo));
                hn0 = __hfma2(wp, t0, hn0);
                hd0 = __hfma2(wq, t0, hd0);
                __half2 t1 = tanh2_fast(__hadd2(__hfma2(wa, v23, wchi), clo));
                hn1 = __hfma2(wp, t1, hn1);
                hd1 = __hfma2(wq, t1, hd1);
            }
            num[0] += __low2float(hn0); num[1] += __high2float(hn0);
            num[2] += __low2float(hn1); num[3] += __high2float(hn1);
            den[0] += __low2float(hd0); den[1] += __high2float(hd0);
            den[2] += __low2float(hd1); den[3] += __high2float(hd1);
        }

        if (g == 1) {
            #pragma unroll
            for (int bb = 0; bb < NB; bb++) { pnum[bb][n] = num[bb]; pden[bb][n] = den[bb]; }
        }
        __syncthreads();   // partials visible; all sv2 reads complete
        if (g == 0) {
            #pragma unroll
            for (int bb = 0; bb < NB; bb++) {
                float nu = num[bb] + pnum[bb][n];
                float de = den[bb] + pden[bb][n];
                vf[bb] = __fdividef(nu, de);
            }
            sv2[n][0] = __floats2half2_rn(vf[0], vf[1]);
            sv2[n][1] = __floats2half2_rn(vf[2], vf[3]);
        }
        __syncthreads();
    }

    // ---- Output (reference returns (v, v) -> possibly 2 copies) ----
    if (g == 0) {
        #pragma unroll
        for (int bb = 0; bb < NB; bb++) {
            int row = r0 + bb;
            for (int c = 0; c < copies; c++)
                out[c * (BATCH * NN) + row * NN + n] = vf[bb];
        }
    }
}

// ---------------------------------------------------------------------------
extern "C" void kernel_launch(void* const* d_in, const int* in_sizes, int n_in,
                              void* d_out, int out_size) {
    const float* inputs = (const float*)d_in[0];
    const float* state  = (const float*)d_in[1];
    const float* map_w  = (const float*)d_in[2];
    const float* map_b  = (const float*)d_in[3];
    const float* smu    = (const float*)d_in[4];
    const float* ssig   = (const float*)d_in[5];
    const float* sW     = (const float*)d_in[6];
    const float* serev  = (const float*)d_in[7];
    const float* mu     = (const float*)d_in[8];
    const float* sigma  = (const float*)d_in[9];
    const float* W      = (const float*)d_in[10];
    const float* erev   = (const float*)d_in[11];
    const float* vleak  = (const float*)d_in[12];
    const float* gleak  = (const float*)d_in[13];
    const float* cm     = (const float*)d_in[14];

    int copies = out_size / (BATCH * NN);
    if (copies < 1) copies = 1;

    pack_rec_kernel<<<NN, NN>>>(mu, sigma, W, erev);
    pack_sen_kernel<<<NI, NN>>>(smu, ssig, sW, serev);
    reduce_k_kernel<<<NN, 128>>>(W, erev, sW, serev, vleak, gleak, cm);
    liquid_main_kernel<<<GRID, NT>>>(inputs, state, map_w, map_b, cm,
                                     (float*)d_out, copies);
}